// round 9
// baseline (speedup 1.0000x reference)
#include <cuda_runtime.h>
#include <math.h>

#define Bsz 16384
#define ND 20
#define DH 64
#define DE 16
#define NOUT 256   // 64 (hc) + 192 (gh)
#define NB 64      // batch elems per block (8 per warp)
#define XPAD 68    // sX row stride in floats (16B-aligned: 68*4=272=17*16)

// Scratch (allowed as __device__ globals). align(16) for float4 access.
__device__ __align__(16) float g_cint[(size_t)Bsz * ND * DH];   // [b][n][k]  84 MB
__device__ __align__(16) float g_G[(size_t)Bsz * ND * DE];      // [b][n][d]  21 MB
__device__ __align__(16) float g_Wcomb[DH * NOUT];              // [k][ Wc1h(64) | Whh(192) ]

__device__ __forceinline__ float tanh_fast(float x) {
    float y; asm("tanh.approx.f32 %0, %1;" : "=f"(y) : "f"(x)); return y;
}
__device__ __forceinline__ float sigmoid_acc(float x) {
    return 1.0f / (1.0f + expf(-x));
}

// ---------------------------------------------------------------------------
// Build fused weight matrix Wcomb[k][c]: c<64 -> Wc1[64+k][c], else Whh[k][c-64]
__global__ void prep_wcomb_kernel(const float* __restrict__ Wc1,
                                  const float* __restrict__ Whh) {
    int idx = blockIdx.x * 256 + threadIdx.x;   // 64 blocks * 256 = 16384
    int k = idx >> 8, c = idx & 255;
    g_Wcomb[idx] = (c < 64) ? Wc1[(64 + k) * 64 + c] : Whh[k * 192 + (c - 64)];
}

// ---------------------------------------------------------------------------
// Precompute: c_int[b][n][:] = inter[n*B+b] @ Wc1[:64] + bc1   (64 outs)
//             G[b][n][:]     = inter[n*B+b] @ We[:64]          (16 outs)
__global__ __launch_bounds__(256, 2) void precompute_kernel(
    const float* __restrict__ inter, const float* __restrict__ Wc1,
    const float* __restrict__ bc1,   const float* __restrict__ We)
{
    extern __shared__ float sm[];
    float* sX  = sm;                 // 256 rows * XPAD
    float* sW  = sm + 256 * XPAD;    // 64*64
    float* sWe = sW + 64 * 64;       // 64*16
    int tid = threadIdx.x;
    size_t rowBase = (size_t)blockIdx.x * 256;

    for (int i = tid; i < 64 * 64; i += 256) sW[i] = Wc1[i];
    for (int i = tid; i < 64 * 16; i += 256) sWe[i] = We[i];
    const float4* in4 = (const float4*)(inter + rowBase * 64);
    for (int i = tid; i < 256 * 16; i += 256) {
        float4 v = in4[i];
        int r = i >> 4, c4 = i & 15;
        *(float4*)&sX[r * XPAD + c4 * 4] = v;
    }
    __syncthreads();

    size_t row = rowBase + tid;
    int n = (int)(row >> 14);          // row / Bsz
    int b = (int)(row & (Bsz - 1));
    const float* xrow = &sX[tid * XPAD];

    float* outc = g_cint + ((size_t)b * ND + n) * DH;
    #pragma unroll
    for (int cc = 0; cc < 4; cc++) {
        float acc[16];
        #pragma unroll
        for (int t = 0; t < 16; t++) acc[t] = bc1[cc * 16 + t];
        for (int j = 0; j < 64; j++) {
            float x = xrow[j];
            const float4* w4 = (const float4*)&sW[j * 64 + cc * 16];
            float4 w0 = w4[0], w1 = w4[1], w2 = w4[2], w3 = w4[3];
            acc[0]  = fmaf(x, w0.x, acc[0]);  acc[1]  = fmaf(x, w0.y, acc[1]);
            acc[2]  = fmaf(x, w0.z, acc[2]);  acc[3]  = fmaf(x, w0.w, acc[3]);
            acc[4]  = fmaf(x, w1.x, acc[4]);  acc[5]  = fmaf(x, w1.y, acc[5]);
            acc[6]  = fmaf(x, w1.z, acc[6]);  acc[7]  = fmaf(x, w1.w, acc[7]);
            acc[8]  = fmaf(x, w2.x, acc[8]);  acc[9]  = fmaf(x, w2.y, acc[9]);
            acc[10] = fmaf(x, w2.z, acc[10]); acc[11] = fmaf(x, w2.w, acc[11]);
            acc[12] = fmaf(x, w3.x, acc[12]); acc[13] = fmaf(x, w3.y, acc[13]);
            acc[14] = fmaf(x, w3.z, acc[14]); acc[15] = fmaf(x, w3.w, acc[15]);
        }
        #pragma unroll
        for (int t = 0; t < 16; t += 4)
            *(float4*)&outc[cc * 16 + t] = make_float4(acc[t], acc[t+1], acc[t+2], acc[t+3]);
    }
    {
        float acc[16];
        #pragma unroll
        for (int t = 0; t < 16; t++) acc[t] = 0.0f;
        for (int j = 0; j < 64; j++) {
            float x = xrow[j];
            const float4* w4 = (const float4*)&sWe[j * 16];
            float4 w0 = w4[0], w1 = w4[1], w2 = w4[2], w3 = w4[3];
            acc[0]  = fmaf(x, w0.x, acc[0]);  acc[1]  = fmaf(x, w0.y, acc[1]);
            acc[2]  = fmaf(x, w0.z, acc[2]);  acc[3]  = fmaf(x, w0.w, acc[3]);
            acc[4]  = fmaf(x, w1.x, acc[4]);  acc[5]  = fmaf(x, w1.y, acc[5]);
            acc[6]  = fmaf(x, w1.z, acc[6]);  acc[7]  = fmaf(x, w1.w, acc[7]);
            acc[8]  = fmaf(x, w2.x, acc[8]);  acc[9]  = fmaf(x, w2.y, acc[9]);
            acc[10] = fmaf(x, w2.z, acc[10]); acc[11] = fmaf(x, w2.w, acc[11]);
            acc[12] = fmaf(x, w3.x, acc[12]); acc[13] = fmaf(x, w3.y, acc[13]);
            acc[14] = fmaf(x, w3.z, acc[14]); acc[15] = fmaf(x, w3.w, acc[15]);
        }
        float* outg = g_G + ((size_t)b * ND + n) * DE;
        #pragma unroll
        for (int t = 0; t < 16; t += 4)
            *(float4*)&outg[t] = make_float4(acc[t], acc[t+1], acc[t+2], acc[t+3]);
    }
}

// ---------------------------------------------------------------------------
// Main persistent decode kernel. Each warp independently owns 8 batch elems
// for the entire 12-step recurrence (no cross-warp deps after init).
__global__ __launch_bounds__(256, 2) void decode_kernel(
    const float* __restrict__ last_x_rel, const float* __restrict__ zo,
    const float* __restrict__ Wih, const float* __restrict__ bih,
    const float* __restrict__ bhh, const float* __restrict__ We,
    const float* __restrict__ be,  const float* __restrict__ Wc2,
    const float* __restrict__ Wo,  const float* __restrict__ bo,
    float* __restrict__ out, int pred_len)
{
    extern __shared__ float sm[];
    float* sh_h   = sm;                    // NB*64
    float* sh_hg  = sh_h + NB * 64;        // NB*256
    float* sh_Wih = sh_hg + NB * 256;      // 16*192
    float* sh_emb = sh_Wih + 16 * 192;     // NB*16
    float* sh_y   = sh_emb + NB * 16;      // NB*2

    const unsigned FULL = 0xffffffffu;
    int tid = threadIdx.x;
    int lane = tid & 31, w = tid >> 5;
    int b0 = blockIdx.x * NB;

    // stage Wih, init h and y
    for (int i = tid; i < 16 * 192; i += 256) sh_Wih[i] = Wih[i];
    for (int i = tid; i < NB * 64; i += 256) sh_h[i] = zo[(size_t)b0 * 64 + i];
    for (int i = tid; i < NB * 2; i += 256) sh_y[i] = last_x_rel[(size_t)b0 * 2 + i];

    // per-lane constants
    int l15 = lane & 15;
    float wc2x = Wc2[l15 * 4], wc2y = Wc2[l15 * 4 + 1];
    float wc2z = Wc2[l15 * 4 + 2], wc2w = Wc2[l15 * 4 + 3];
    float weY0 = We[64 * 16 + l15], weY1 = We[65 * 16 + l15], be_l = be[l15];
    float bih6[6], bhh6[6];
    #pragma unroll
    for (int i = 0; i < 6; i++) { bih6[i] = bih[lane + 32 * i]; bhh6[i] = bhh[lane + 32 * i]; }
    float wo00 = Wo[lane * 2], wo01 = Wo[lane * 2 + 1];
    float wo10 = Wo[(lane + 32) * 2], wo11 = Wo[(lane + 32) * 2 + 1];
    float bo0 = bo[0], bo1 = bo[1];

    __syncthreads();

    for (int step = 0; step < pred_len; step++) {
        // ---- Phase A: hg[b][0:256] = h[b] @ Wcomb  (8 b's, lane owns 8 cols)
        {
            float acc[8][8];
            #pragma unroll
            for (int j = 0; j < 8; j++)
                #pragma unroll
                for (int t = 0; t < 8; t++) acc[j][t] = 0.0f;
            const float* hb = &sh_h[(w * 8) * 64];
            #pragma unroll 4
            for (int k = 0; k < 64; k++) {
                const float4* wp = (const float4*)(g_Wcomb + k * 256 + lane * 8);
                float4 wa = wp[0], wb = wp[1];
                #pragma unroll
                for (int j = 0; j < 8; j++) {
                    float x = hb[j * 64 + k];
                    acc[j][0] = fmaf(x, wa.x, acc[j][0]);
                    acc[j][1] = fmaf(x, wa.y, acc[j][1]);
                    acc[j][2] = fmaf(x, wa.z, acc[j][2]);
                    acc[j][3] = fmaf(x, wa.w, acc[j][3]);
                    acc[j][4] = fmaf(x, wb.x, acc[j][4]);
                    acc[j][5] = fmaf(x, wb.y, acc[j][5]);
                    acc[j][6] = fmaf(x, wb.z, acc[j][6]);
                    acc[j][7] = fmaf(x, wb.w, acc[j][7]);
                }
            }
            #pragma unroll
            for (int j = 0; j < 8; j++) {
                float* o = &sh_hg[(w * 8 + j) * 256 + lane * 8];
                *(float4*)o       = make_float4(acc[j][0], acc[j][1], acc[j][2], acc[j][3]);
                *(float4*)(o + 4) = make_float4(acc[j][4], acc[j][5], acc[j][6], acc[j][7]);
            }
        }
        __syncwarp();

        // ---- Phases B..F per b (warp-local)
        for (int jb = 0; jb < 8; jb++) {
            int b = w * 8 + jb;
            int bg = b0 + b;

            // Phase B: attention logits s_n = Wc2 . tanh(c_int + hc)
            const float* cbase = g_cint + (size_t)bg * (ND * DH);
            float4 hc = *(const float4*)&sh_hg[b * 256 + l15 * 4];
            float sv = -1e30f;
            #pragma unroll
            for (int it = 0; it < 10; it++) {
                float4 c4 = *(const float4*)(cbase + it * 128 + lane * 4);
                float part = wc2x * tanh_fast(c4.x + hc.x);
                part = fmaf(wc2y, tanh_fast(c4.y + hc.y), part);
                part = fmaf(wc2z, tanh_fast(c4.z + hc.z), part);
                part = fmaf(wc2w, tanh_fast(c4.w + hc.w), part);
                float s = part;
                s += __shfl_xor_sync(FULL, s, 1);
                s += __shfl_xor_sync(FULL, s, 2);
                s += __shfl_xor_sync(FULL, s, 4);
                s += __shfl_xor_sync(FULL, s, 8);
                float so = __shfl_xor_sync(FULL, s, 16);
                if ((lane >> 1) == it) {
                    bool own = (lane & 1) ? (lane >= 16) : (lane < 16);
                    sv = own ? s : so;
                }
            }
            // Phase C: softmax over lanes 0..19
            float mx = sv;
            mx = fmaxf(mx, __shfl_xor_sync(FULL, mx, 16));
            mx = fmaxf(mx, __shfl_xor_sync(FULL, mx, 8));
            mx = fmaxf(mx, __shfl_xor_sync(FULL, mx, 4));
            mx = fmaxf(mx, __shfl_xor_sync(FULL, mx, 2));
            mx = fmaxf(mx, __shfl_xor_sync(FULL, mx, 1));
            float e = __expf(sv - mx);
            float se = e;
            se += __shfl_xor_sync(FULL, se, 16);
            se += __shfl_xor_sync(FULL, se, 8);
            se += __shfl_xor_sync(FULL, se, 4);
            se += __shfl_xor_sync(FULL, se, 2);
            se += __shfl_xor_sync(FULL, se, 1);
            float alpha = e / se;   // lanes>=20 hold 0

            // Phase D: embg = sum_n alpha_n * G[b][n][:], then emb
            {
                int d = l15, half = lane >> 4;
                float accg = 0.0f;
                const float* gbase = g_G + (size_t)bg * (ND * DE) + d;
                #pragma unroll
                for (int i = 0; i < 10; i++) {
                    int n = 2 * i + half;
                    float a = __shfl_sync(FULL, alpha, n);
                    accg = fmaf(a, gbase[n * 16], accg);
                }
                accg += __shfl_xor_sync(FULL, accg, 16);
                float y0 = sh_y[b * 2], y1 = sh_y[b * 2 + 1];
                float emb = accg + y0 * weY0 + y1 * weY1 + be_l;
                if (lane < 16) sh_emb[b * 16 + d] = emb;
            }
            __syncwarp();

            // Phase E: gi[6] = bih + emb @ Wih  (cols lane+32*i)
            float ev[16];
            {
                const float4* e4 = (const float4*)&sh_emb[b * 16];
                float4 a = e4[0], bb = e4[1], c = e4[2], dd = e4[3];
                ev[0]=a.x; ev[1]=a.y; ev[2]=a.z; ev[3]=a.w;
                ev[4]=bb.x; ev[5]=bb.y; ev[6]=bb.z; ev[7]=bb.w;
                ev[8]=c.x; ev[9]=c.y; ev[10]=c.z; ev[11]=c.w;
                ev[12]=dd.x; ev[13]=dd.y; ev[14]=dd.z; ev[15]=dd.w;
            }
            float gi[6];
            #pragma unroll
            for (int i = 0; i < 6; i++) gi[i] = bih6[i];
            #pragma unroll
            for (int k = 0; k < 16; k++) {
                #pragma unroll
                for (int i = 0; i < 6; i++)
                    gi[i] = fmaf(ev[k], sh_Wih[k * 192 + lane + 32 * i], gi[i]);
            }

            // Phase F: GRU gates + output
            float gh[6];
            #pragma unroll
            for (int i = 0; i < 6; i++) gh[i] = sh_hg[b * 256 + 64 + lane + 32 * i];
            float r0 = sigmoid_acc(gi[0] + gh[0] + bhh6[0]);
            float r1 = sigmoid_acc(gi[1] + gh[1] + bhh6[1]);
            float z0 = sigmoid_acc(gi[2] + gh[2] + bhh6[2]);
            float z1 = sigmoid_acc(gi[3] + gh[3] + bhh6[3]);
            float n0 = tanhf(gi[4] + r0 * (gh[4] + bhh6[4]));
            float n1 = tanhf(gi[5] + r1 * (gh[5] + bhh6[5]));
            float h0 = sh_h[b * 64 + lane];
            float h1 = sh_h[b * 64 + lane + 32];
            float hn0 = n0 + z0 * (h0 - n0);
            float hn1 = n1 + z1 * (h1 - n1);
            sh_h[b * 64 + lane] = hn0;
            sh_h[b * 64 + lane + 32] = hn1;

            float p0 = hn0 * wo00 + hn1 * wo10;
            float p1 = hn0 * wo01 + hn1 * wo11;
            p0 += __shfl_xor_sync(FULL, p0, 16); p1 += __shfl_xor_sync(FULL, p1, 16);
            p0 += __shfl_xor_sync(FULL, p0, 8);  p1 += __shfl_xor_sync(FULL, p1, 8);
            p0 += __shfl_xor_sync(FULL, p0, 4);  p1 += __shfl_xor_sync(FULL, p1, 4);
            p0 += __shfl_xor_sync(FULL, p0, 2);  p1 += __shfl_xor_sync(FULL, p1, 2);
            p0 += __shfl_xor_sync(FULL, p0, 1);  p1 += __shfl_xor_sync(FULL, p1, 1);
            if (lane == 0) {
                float yo0 = p0 + bo0, yo1 = p1 + bo1;
                sh_y[b * 2] = yo0; sh_y[b * 2 + 1] = yo1;
                out[((size_t)step * Bsz + bg) * 2]     = yo0;
                out[((size_t)step * Bsz + bg) * 2 + 1] = yo1;
            }
            __syncwarp();
        }
        __syncwarp();
    }
}

// ---------------------------------------------------------------------------
extern "C" void kernel_launch(void* const* d_in, const int* in_sizes, int n_in,
                              void* d_out, int out_size) {
    // pred_len may arrive as a size-1 scalar input; detect and offset.
    int off = (in_sizes[0] == 1) ? 1 : 0;
    const float* last_x = (const float*)d_in[off + 0];
    const float* zo     = (const float*)d_in[off + 1];
    // d_in[off+2] = zg (unused by the math)
    const float* inter  = (const float*)d_in[off + 3];
    const float* We     = (const float*)d_in[off + 4];
    const float* be     = (const float*)d_in[off + 5];
    const float* Wih    = (const float*)d_in[off + 6];
    const float* Whh    = (const float*)d_in[off + 7];
    const float* bih    = (const float*)d_in[off + 8];
    const float* bhh    = (const float*)d_in[off + 9];
    const float* Wc1    = (const float*)d_in[off + 10];
    const float* bc1    = (const float*)d_in[off + 11];
    const float* Wc2    = (const float*)d_in[off + 12];
    // d_in[off+13] = bc2 (constant over n -> cancels in softmax)
    const float* Wo     = (const float*)d_in[off + 14];
    const float* bo     = (const float*)d_in[off + 15];
    float* out = (float*)d_out;
    int pred_len = out_size / (2 * Bsz);

    const int PRE_SMEM = (256 * XPAD + 64 * 64 + 64 * 16) * 4;          // 90112 B
    const int DEC_SMEM = (NB * 64 + NB * 256 + 16 * 192 + NB * 16 + NB * 2) * 4;  // 98816 B
    // Idempotent; persists from the (non-captured) correctness call.
    cudaFuncSetAttribute(precompute_kernel, cudaFuncAttributeMaxDynamicSharedMemorySize, PRE_SMEM);
    cudaFuncSetAttribute(decode_kernel, cudaFuncAttributeMaxDynamicSharedMemorySize, DEC_SMEM);

    prep_wcomb_kernel<<<64, 256>>>(Wc1, Whh);
    precompute_kernel<<<(Bsz * ND) / 256, 256, PRE_SMEM>>>(inter, Wc1, bc1, We);
    decode_kernel<<<Bsz / NB, 256, DEC_SMEM>>>(last_x, zo, Wih, bih, bhh,
                                               We, be, Wc2, Wo, bo, out, pred_len);
}

// round 14
// speedup vs baseline: 1.0975x; 1.0975x over previous
#include <cuda_runtime.h>
#include <math.h>

#define Bsz 16384
#define ND 20
#define DH 64
#define DE 16
#define NOUT 256   // 64 (hc) + 192 (gh)
#define NB 64      // batch elems per block (8 per warp)
#define XPAD 68    // sX row stride in floats (16B-aligned: 68*4=272=17*16)

// Scratch (allowed as __device__ globals). align(16) for vector access.
__device__ __align__(16) float g_cint[(size_t)Bsz * ND * DH];   // [b][n][k]  84 MB
__device__ __align__(16) float g_G[(size_t)Bsz * ND * DE];      // [b][n][d]  21 MB
__device__ __align__(16) float g_Wcomb[DH * NOUT];              // [k][ Wc1h(64) | Whh(192) ]

__device__ __forceinline__ float tanh_fast(float x) {
    float y; asm("tanh.approx.f32 %0, %1;" : "=f"(y) : "f"(x)); return y;
}
__device__ __forceinline__ float sigmoid_fast(float x) {
    return __fdividef(1.0f, 1.0f + __expf(-x));
}
// Packed f32x2 helpers (Blackwell): one instruction, two fp32 FMAs, full precision.
__device__ __forceinline__ unsigned long long pack2(float lo, float hi) {
    unsigned long long r;
    asm("mov.b64 %0, {%1, %2};" : "=l"(r) : "f"(lo), "f"(hi));
    return r;
}
__device__ __forceinline__ unsigned long long fma2(unsigned long long a,
                                                   unsigned long long b,
                                                   unsigned long long c) {
    unsigned long long d;
    asm("fma.rn.f32x2 %0, %1, %2, %3;" : "=l"(d) : "l"(a), "l"(b), "l"(c));
    return d;
}

// ---------------------------------------------------------------------------
// Build fused weight matrix Wcomb[k][c]: c<64 -> Wc1[64+k][c], else Whh[k][c-64]
__global__ void prep_wcomb_kernel(const float* __restrict__ Wc1,
                                  const float* __restrict__ Whh) {
    int idx = blockIdx.x * 256 + threadIdx.x;   // 64 blocks * 256 = 16384
    int k = idx >> 8, c = idx & 255;
    g_Wcomb[idx] = (c < 64) ? Wc1[(64 + k) * 64 + c] : Whh[k * 192 + (c - 64)];
}

// ---------------------------------------------------------------------------
// Precompute: c_int[b][n][:] = inter[n*B+b] @ Wc1[:64] + bc1   (64 outs)
//             G[b][n][:]     = inter[n*B+b] @ We[:64]          (16 outs)
__global__ __launch_bounds__(256, 2) void precompute_kernel(
    const float* __restrict__ inter, const float* __restrict__ Wc1,
    const float* __restrict__ bc1,   const float* __restrict__ We)
{
    extern __shared__ float sm[];
    float* sX  = sm;                 // 256 rows * XPAD
    float* sW  = sm + 256 * XPAD;    // 64*64
    float* sWe = sW + 64 * 64;       // 64*16
    int tid = threadIdx.x;
    size_t rowBase = (size_t)blockIdx.x * 256;

    for (int i = tid; i < 64 * 64; i += 256) sW[i] = Wc1[i];
    for (int i = tid; i < 64 * 16; i += 256) sWe[i] = We[i];
    const float4* in4 = (const float4*)(inter + rowBase * 64);
    for (int i = tid; i < 256 * 16; i += 256) {
        float4 v = in4[i];
        int r = i >> 4, c4 = i & 15;
        *(float4*)&sX[r * XPAD + c4 * 4] = v;
    }
    __syncthreads();

    size_t row = rowBase + tid;
    int n = (int)(row >> 14);          // row / Bsz
    int b = (int)(row & (Bsz - 1));
    const float* xrow = &sX[tid * XPAD];

    float* outc = g_cint + ((size_t)b * ND + n) * DH;
    #pragma unroll
    for (int cc = 0; cc < 4; cc++) {
        unsigned long long acc8[8];
        #pragma unroll
        for (int t = 0; t < 8; t++)
            acc8[t] = pack2(bc1[cc * 16 + 2 * t], bc1[cc * 16 + 2 * t + 1]);
        for (int j = 0; j < 64; j++) {
            float x = xrow[j];
            unsigned long long xx = pack2(x, x);
            const ulonglong2* w4 = (const ulonglong2*)&sW[j * 64 + cc * 16];
            ulonglong2 p0 = w4[0], p1 = w4[1], p2 = w4[2], p3 = w4[3];
            acc8[0] = fma2(xx, p0.x, acc8[0]); acc8[1] = fma2(xx, p0.y, acc8[1]);
            acc8[2] = fma2(xx, p1.x, acc8[2]); acc8[3] = fma2(xx, p1.y, acc8[3]);
            acc8[4] = fma2(xx, p2.x, acc8[4]); acc8[5] = fma2(xx, p2.y, acc8[5]);
            acc8[6] = fma2(xx, p3.x, acc8[6]); acc8[7] = fma2(xx, p3.y, acc8[7]);
        }
        ulonglong2* oc = (ulonglong2*)(outc + cc * 16);
        oc[0] = make_ulonglong2(acc8[0], acc8[1]);
        oc[1] = make_ulonglong2(acc8[2], acc8[3]);
        oc[2] = make_ulonglong2(acc8[4], acc8[5]);
        oc[3] = make_ulonglong2(acc8[6], acc8[7]);
    }
    {
        unsigned long long acc8[8];
        #pragma unroll
        for (int t = 0; t < 8; t++) acc8[t] = 0ull;   // (0.0f, 0.0f)
        for (int j = 0; j < 64; j++) {
            float x = xrow[j];
            unsigned long long xx = pack2(x, x);
            const ulonglong2* w4 = (const ulonglong2*)&sWe[j * 16];
            ulonglong2 p0 = w4[0], p1 = w4[1], p2 = w4[2], p3 = w4[3];
            acc8[0] = fma2(xx, p0.x, acc8[0]); acc8[1] = fma2(xx, p0.y, acc8[1]);
            acc8[2] = fma2(xx, p1.x, acc8[2]); acc8[3] = fma2(xx, p1.y, acc8[3]);
            acc8[4] = fma2(xx, p2.x, acc8[4]); acc8[5] = fma2(xx, p2.y, acc8[5]);
            acc8[6] = fma2(xx, p3.x, acc8[6]); acc8[7] = fma2(xx, p3.y, acc8[7]);
        }
        ulonglong2* og = (ulonglong2*)(g_G + ((size_t)b * ND + n) * DE);
        og[0] = make_ulonglong2(acc8[0], acc8[1]);
        og[1] = make_ulonglong2(acc8[2], acc8[3]);
        og[2] = make_ulonglong2(acc8[4], acc8[5]);
        og[3] = make_ulonglong2(acc8[6], acc8[7]);
    }
}

// ---------------------------------------------------------------------------
// Main persistent decode kernel. Each warp independently owns 8 batch elems
// for the entire 12-step recurrence (no cross-warp deps after init).
__global__ __launch_bounds__(256, 2) void decode_kernel(
    const float* __restrict__ last_x_rel, const float* __restrict__ zo,
    const float* __restrict__ Wih, const float* __restrict__ bih,
    const float* __restrict__ bhh, const float* __restrict__ We,
    const float* __restrict__ be,  const float* __restrict__ Wc2,
    const float* __restrict__ Wo,  const float* __restrict__ bo,
    float* __restrict__ out, int pred_len)
{
    extern __shared__ float sm[];
    float* sh_h   = sm;                    // NB*64
    float* sh_hg  = sh_h + NB * 64;        // NB*256
    float* sh_Wih = sh_hg + NB * 256;      // 16*192
    float* sh_emb = sh_Wih + 16 * 192;     // NB*16
    float* sh_y   = sh_emb + NB * 16;      // NB*2

    const unsigned FULL = 0xffffffffu;
    int tid = threadIdx.x;
    int lane = tid & 31, w = tid >> 5;
    int b0 = blockIdx.x * NB;

    // stage Wih, init h and y
    for (int i = tid; i < 16 * 192; i += 256) sh_Wih[i] = Wih[i];
    for (int i = tid; i < NB * 64; i += 256) sh_h[i] = zo[(size_t)b0 * 64 + i];
    for (int i = tid; i < NB * 2; i += 256) sh_y[i] = last_x_rel[(size_t)b0 * 2 + i];

    // per-lane constants
    int l15 = lane & 15;
    float wc2x = Wc2[l15 * 4], wc2y = Wc2[l15 * 4 + 1];
    float wc2z = Wc2[l15 * 4 + 2], wc2w = Wc2[l15 * 4 + 3];
    float weY0 = We[64 * 16 + l15], weY1 = We[65 * 16 + l15], be_l = be[l15];
    float bih6[6], bhh6[6];
    #pragma unroll
    for (int i = 0; i < 6; i++) { bih6[i] = bih[lane + 32 * i]; bhh6[i] = bhh[lane + 32 * i]; }
    float wo00 = Wo[lane * 2], wo01 = Wo[lane * 2 + 1];
    float wo10 = Wo[(lane + 32) * 2], wo11 = Wo[(lane + 32) * 2 + 1];
    float bo0 = bo[0], bo1 = bo[1];

    __syncthreads();

    for (int step = 0; step < pred_len; step++) {
        // ---- Phase A: hg[b][0:256] = h[b] @ Wcomb  (packed f32x2: lane owns
        //      8 cols = 4 packed pairs per b, 8 b's per warp)
        {
            unsigned long long acc[8][4];
            #pragma unroll
            for (int j = 0; j < 8; j++)
                #pragma unroll
                for (int t = 0; t < 4; t++) acc[j][t] = 0ull;
            const float* hb = &sh_h[(w * 8) * 64];
            #pragma unroll 4
            for (int k = 0; k < 64; k++) {
                const ulonglong2* wp = (const ulonglong2*)(g_Wcomb + k * 256 + lane * 8);
                ulonglong2 wa = wp[0], wb = wp[1];
                #pragma unroll
                for (int j = 0; j < 8; j++) {
                    float x = hb[j * 64 + k];
                    unsigned long long xx = pack2(x, x);
                    acc[j][0] = fma2(xx, wa.x, acc[j][0]);
                    acc[j][1] = fma2(xx, wa.y, acc[j][1]);
                    acc[j][2] = fma2(xx, wb.x, acc[j][2]);
                    acc[j][3] = fma2(xx, wb.y, acc[j][3]);
                }
            }
            #pragma unroll
            for (int j = 0; j < 8; j++) {
                ulonglong2* o = (ulonglong2*)&sh_hg[(w * 8 + j) * 256 + lane * 8];
                o[0] = make_ulonglong2(acc[j][0], acc[j][1]);
                o[1] = make_ulonglong2(acc[j][2], acc[j][3]);
            }
        }
        __syncwarp();

        // ---- Phases B..F per b (warp-local)
        for (int jb = 0; jb < 8; jb++) {
            int b = w * 8 + jb;
            int bg = b0 + b;

            // Phase B: attention logits s_n = Wc2 . tanh(c_int + hc)
            const float* cbase = g_cint + (size_t)bg * (ND * DH);
            float4 hc = *(const float4*)&sh_hg[b * 256 + l15 * 4];
            float sv = -1e30f;
            #pragma unroll
            for (int it = 0; it < 10; it++) {
                float4 c4 = *(const float4*)(cbase + it * 128 + lane * 4);
                float part = wc2x * tanh_fast(c4.x + hc.x);
                part = fmaf(wc2y, tanh_fast(c4.y + hc.y), part);
                part = fmaf(wc2z, tanh_fast(c4.z + hc.z), part);
                part = fmaf(wc2w, tanh_fast(c4.w + hc.w), part);
                float s = part;
                s += __shfl_xor_sync(FULL, s, 1);
                s += __shfl_xor_sync(FULL, s, 2);
                s += __shfl_xor_sync(FULL, s, 4);
                s += __shfl_xor_sync(FULL, s, 8);
                float so = __shfl_xor_sync(FULL, s, 16);
                if ((lane >> 1) == it) {
                    bool own = (lane & 1) ? (lane >= 16) : (lane < 16);
                    sv = own ? s : so;
                }
            }
            // Phase C: softmax over lanes 0..19
            float mx = sv;
            mx = fmaxf(mx, __shfl_xor_sync(FULL, mx, 16));
            mx = fmaxf(mx, __shfl_xor_sync(FULL, mx, 8));
            mx = fmaxf(mx, __shfl_xor_sync(FULL, mx, 4));
            mx = fmaxf(mx, __shfl_xor_sync(FULL, mx, 2));
            mx = fmaxf(mx, __shfl_xor_sync(FULL, mx, 1));
            float e = __expf(sv - mx);
            float se = e;
            se += __shfl_xor_sync(FULL, se, 16);
            se += __shfl_xor_sync(FULL, se, 8);
            se += __shfl_xor_sync(FULL, se, 4);
            se += __shfl_xor_sync(FULL, se, 2);
            se += __shfl_xor_sync(FULL, se, 1);
            float alpha = __fdividef(e, se);   // lanes>=20 hold 0

            // Phase D: embg = sum_n alpha_n * G[b][n][:], then emb
            {
                int d = l15, half = lane >> 4;
                float accg = 0.0f;
                const float* gbase = g_G + (size_t)bg * (ND * DE) + d;
                #pragma unroll
                for (int i = 0; i < 10; i++) {
                    int n = 2 * i + half;
                    float a = __shfl_sync(FULL, alpha, n);
                    accg = fmaf(a, gbase[n * 16], accg);
                }
                accg += __shfl_xor_sync(FULL, accg, 16);
                float y0 = sh_y[b * 2], y1 = sh_y[b * 2 + 1];
                float emb = accg + y0 * weY0 + y1 * weY1 + be_l;
                if (lane < 16) sh_emb[b * 16 + d] = emb;
            }
            __syncwarp();

            // Phase E: gi[6] = bih + emb @ Wih  (cols lane+32*i)
            float ev[16];
            {
                const float4* e4 = (const float4*)&sh_emb[b * 16];
                float4 a = e4[0], bb = e4[1], c = e4[2], dd = e4[3];
                ev[0]=a.x; ev[1]=a.y; ev[2]=a.z; ev[3]=a.w;
                ev[4]=bb.x; ev[5]=bb.y; ev[6]=bb.z; ev[7]=bb.w;
                ev[8]=c.x; ev[9]=c.y; ev[10]=c.z; ev[11]=c.w;
                ev[12]=dd.x; ev[13]=dd.y; ev[14]=dd.z; ev[15]=dd.w;
            }
            float gi[6];
            #pragma unroll
            for (int i = 0; i < 6; i++) gi[i] = bih6[i];
            #pragma unroll
            for (int k = 0; k < 16; k++) {
                #pragma unroll
                for (int i = 0; i < 6; i++)
                    gi[i] = fmaf(ev[k], sh_Wih[k * 192 + lane + 32 * i], gi[i]);
            }

            // Phase F: GRU gates + output
            float gh[6];
            #pragma unroll
            for (int i = 0; i < 6; i++) gh[i] = sh_hg[b * 256 + 64 + lane + 32 * i];
            float r0 = sigmoid_fast(gi[0] + gh[0] + bhh6[0]);
            float r1 = sigmoid_fast(gi[1] + gh[1] + bhh6[1]);
            float z0 = sigmoid_fast(gi[2] + gh[2] + bhh6[2]);
            float z1 = sigmoid_fast(gi[3] + gh[3] + bhh6[3]);
            float n0 = tanhf(gi[4] + r0 * (gh[4] + bhh6[4]));
            float n1 = tanhf(gi[5] + r1 * (gh[5] + bhh6[5]));
            float h0 = sh_h[b * 64 + lane];
            float h1 = sh_h[b * 64 + lane + 32];
            float hn0 = n0 + z0 * (h0 - n0);
            float hn1 = n1 + z1 * (h1 - n1);
            sh_h[b * 64 + lane] = hn0;
            sh_h[b * 64 + lane + 32] = hn1;

            float p0 = hn0 * wo00 + hn1 * wo10;
            float p1 = hn0 * wo01 + hn1 * wo11;
            p0 += __shfl_xor_sync(FULL, p0, 16); p1 += __shfl_xor_sync(FULL, p1, 16);
            p0 += __shfl_xor_sync(FULL, p0, 8);  p1 += __shfl_xor_sync(FULL, p1, 8);
            p0 += __shfl_xor_sync(FULL, p0, 4);  p1 += __shfl_xor_sync(FULL, p1, 4);
            p0 += __shfl_xor_sync(FULL, p0, 2);  p1 += __shfl_xor_sync(FULL, p1, 2);
            p0 += __shfl_xor_sync(FULL, p0, 1);  p1 += __shfl_xor_sync(FULL, p1, 1);
            if (lane == 0) {
                float yo0 = p0 + bo0, yo1 = p1 + bo1;
                sh_y[b * 2] = yo0; sh_y[b * 2 + 1] = yo1;
                out[((size_t)step * Bsz + bg) * 2]     = yo0;
                out[((size_t)step * Bsz + bg) * 2 + 1] = yo1;
            }
            __syncwarp();
        }
        __syncwarp();
    }
}

// ---------------------------------------------------------------------------
extern "C" void kernel_launch(void* const* d_in, const int* in_sizes, int n_in,
                              void* d_out, int out_size) {
    // pred_len may arrive as a size-1 scalar input; detect and offset.
    int off = (in_sizes[0] == 1) ? 1 : 0;
    const float* last_x = (const float*)d_in[off + 0];
    const float* zo     = (const float*)d_in[off + 1];
    // d_in[off+2] = zg (unused by the math)
    const float* inter  = (const float*)d_in[off + 3];
    const float* We     = (const float*)d_in[off + 4];
    const float* be     = (const float*)d_in[off + 5];
    const float* Wih    = (const float*)d_in[off + 6];
    const float* Whh    = (const float*)d_in[off + 7];
    const float* bih    = (const float*)d_in[off + 8];
    const float* bhh    = (const float*)d_in[off + 9];
    const float* Wc1    = (const float*)d_in[off + 10];
    const float* bc1    = (const float*)d_in[off + 11];
    const float* Wc2    = (const float*)d_in[off + 12];
    // d_in[off+13] = bc2 (constant over n -> cancels in softmax)
    const float* Wo     = (const float*)d_in[off + 14];
    const float* bo     = (const float*)d_in[off + 15];
    float* out = (float*)d_out;
    int pred_len = out_size / (2 * Bsz);

    const int PRE_SMEM = (256 * XPAD + 64 * 64 + 64 * 16) * 4;          // 90112 B
    const int DEC_SMEM = (NB * 64 + NB * 256 + 16 * 192 + NB * 16 + NB * 2) * 4;  // 98816 B
    // Idempotent; persists from the (non-captured) correctness call.
    cudaFuncSetAttribute(precompute_kernel, cudaFuncAttributeMaxDynamicSharedMemorySize, PRE_SMEM);
    cudaFuncSetAttribute(decode_kernel, cudaFuncAttributeMaxDynamicSharedMemorySize, DEC_SMEM);

    prep_wcomb_kernel<<<64, 256>>>(Wc1, Whh);
    precompute_kernel<<<(Bsz * ND) / 256, 256, PRE_SMEM>>>(inter, Wc1, bc1, We);
    decode_kernel<<<Bsz / NB, 256, DEC_SMEM>>>(last_x, zo, Wih, bih, bhh,
                                               We, be, Wc2, Wo, bo, out, pred_len);
}